// round 5
// baseline (speedup 1.0000x reference)
#include <cuda_runtime.h>
#include <cuda_bf16.h>
#include <math.h>

// NeuralNDCG, N=4096. Persistent kernel, 128 blocks x 1024 threads (64-reg cap
// via launch_bounds -> 50% occ). mat_t = diag(R) U diag(C); U = exp(c_i p_j -
// B_j - m_i) fixed bf16 (32MB, L2-resident). Per iteration: pass1 row-dots
// (L2 sweep, warp-pre-reduced partials -> 16 floats/row in smem) -> fresh R ->
// pass2 colsums (L1 re-read) -> half-combined single RED per column -> grid
// barrier. Block = two independent 512-thread halves (16 rows each) synced by
// named barriers. Static smem ~35KB (under the 48KB cap).

#define NNV 4096
#define NBLK 128
#define TPB 1024
#define ROWS_PB 32
#define HROWS 16
#define EPSF 1e-10f
#define ITERS 50

__device__ __nv_bfloat16 g_mat[(size_t)NNV * NNV];   // 32 MB
__device__ float g_Bv[NNV];
__device__ float g_Rb[2][NNV];
__device__ float g_Cb[2][NNV];
__device__ float g_av[3][NNV];
__device__ float g_rowdcg[NNV];
__device__ float g_idcgPart[NBLK];
__device__ unsigned g_barCnt, g_barGen;

__device__ __forceinline__ void grid_barrier() {
    __syncthreads();
    if (threadIdx.x == 0) {
        __threadfence();
        unsigned g = *((volatile unsigned*)&g_barGen);
        if (atomicAdd(&g_barCnt, 1u) == NBLK - 1) {
            atomicExch(&g_barCnt, 0u);
            __threadfence();
            atomicAdd(&g_barGen, 1u);
        } else {
            while (*((volatile unsigned*)&g_barGen) == g) __nanosleep(32);
        }
        __threadfence();
    }
    __syncthreads();
}

__device__ __forceinline__ void half_sync(int h) {
    asm volatile("bar.sync %0, 512;" :: "r"(h + 1) : "memory");
}

__device__ __forceinline__ float wredsum(float v) {
    #pragma unroll
    for (int o = 16; o > 0; o >>= 1) v += __shfl_xor_sync(0xffffffffu, v, o);
    return v;
}
__device__ __forceinline__ float wredmax(float v) {
    #pragma unroll
    for (int o = 16; o > 0; o >>= 1) v = fmaxf(v, __shfl_xor_sync(0xffffffffu, v, o));
    return v;
}
__device__ __forceinline__ void unpack8(uint4 q, float* v) {
    const __nv_bfloat162* hh = reinterpret_cast<const __nv_bfloat162*>(&q);
    #pragma unroll
    for (int p = 0; p < 4; p++) {
        float2 f = __bfloat1622float2(hh[p]);
        v[2 * p] = f.x; v[2 * p + 1] = f.y;
    }
}

__global__ void __launch_bounds__(TPB, 1)
ndcg_kernel(const float* __restrict__ pred, const float* __restrict__ target,
            float* __restrict__ out)
{
    __shared__ float s_buf[2 * NNV];        // 32KB: init/build staging; comb (first 4096)
    __shared__ float s_pb[2][HROWS][17];    // warp-pre-reduced row partials
    __shared__ float s_rn[2][HROWS];
    __shared__ float s_red[32];

    const int tid = threadIdx.x, bid = blockIdx.x;
    const int wid = tid >> 5, lane = tid & 31;
    const int h = tid >> 9, ht = tid & 511;
    const int hw = wid & 15;                // warp index within half

    float* p_s = s_buf;
    float* t_s = s_buf + NNV;

    // ================= INIT: zeros, B[j], ideal DCG =================
    {
        int g = bid * TPB + tid;
        if (g < NNV)            g_av[0][g] = 0.0f;
        else if (g < 2 * NNV)   g_av[1][g - NNV] = 0.0f;
        else if (g < 3 * NNV)   g_Cb[0][g - 2 * NNV] = 1.0f;
    }
    for (int k = tid; k < NNV; k += TPB) { p_s[k] = pred[k]; t_s[k] = target[k]; }
    __syncthreads();
    {
        int j = bid * ROWS_PB + wid;        // warp per j, 32 j per block
        float pj = p_s[j], tj = t_s[j];
        float acc = 0.0f; int rank = 0;
        #pragma unroll 4
        for (int k = 0; k < 128; k++) {
            acc += fabsf(pj - p_s[k * 32 + lane]);
            rank += (t_s[k * 32 + lane] > tj);
        }
        acc = wredsum(acc);
        #pragma unroll
        for (int o = 16; o > 0; o >>= 1) rank += __shfl_xor_sync(0xffffffffu, rank, o);
        if (lane == 0) {
            g_Bv[j] = acc;
            s_red[wid] = (exp2f(tj) - 1.0f) / log2f((float)rank + 2.0f);
        }
        __syncthreads();
        if (tid == 0) {
            float s = 0.0f;
            for (int k = 0; k < 32; k++) s += s_red[k];
            g_idcgPart[bid] = s;
        }
    }
    grid_barrier();

    // ================= BUILD U (bf16), R0 = 1/Z (warp per row) =================
    for (int k = tid; k < NNV; k += TPB) t_s[k] = __ldcg(&g_Bv[k]);   // B into t_s
    __syncthreads();
    {
        int i = bid * ROWS_PB + wid;
        float ci = (float)(NNV - 1 - 2 * i);
        float m = -INFINITY;
        for (int c = 0; c < 16; c++) {
            int j0 = (c * 32 + lane) * 8;
            #pragma unroll
            for (int mm = 0; mm < 8; mm++)
                m = fmaxf(m, fmaf(ci, p_s[j0 + mm], -t_s[j0 + mm]));
        }
        m = wredmax(m);
        float z = 0.0f;
        uint4* rq = reinterpret_cast<uint4*>(g_mat + (size_t)i * NNV);
        for (int c = 0; c < 16; c++) {
            int j0 = (c * 32 + lane) * 8;
            float e[8];
            #pragma unroll
            for (int mm = 0; mm < 8; mm++) {
                e[mm] = __expf(fmaf(ci, p_s[j0 + mm], -t_s[j0 + mm]) - m);
                z += e[mm];
            }
            uint4 q;
            __nv_bfloat162* hq = reinterpret_cast<__nv_bfloat162*>(&q);
            hq[0] = __floats2bfloat162_rn(e[0], e[1]);
            hq[1] = __floats2bfloat162_rn(e[2], e[3]);
            hq[2] = __floats2bfloat162_rn(e[4], e[5]);
            hq[3] = __floats2bfloat162_rn(e[6], e[7]);
            rq[c * 32 + lane] = q;
        }
        z = wredsum(z);
        if (lane == 0) g_Rb[0][i] = 1.0f / z;
    }
    grid_barrier();

    // ================= BOOTSTRAP a0 = U^T R0 =================
    {
        const int rbase = bid * ROWS_PB + h * HROWS;
        float colacc[8];
        #pragma unroll
        for (int mm = 0; mm < 8; mm++) colacc[mm] = 0.0f;
        #pragma unroll 4
        for (int r = 0; r < HROWS; r++) {
            float Ri = __ldcg(&g_Rb[0][rbase + r]);
            uint4 q = reinterpret_cast<const uint4*>(g_mat + (size_t)(rbase + r) * NNV)[ht];
            float v[8]; unpack8(q, v);
            #pragma unroll
            for (int mm = 0; mm < 8; mm++) colacc[mm] = fmaf(Ri, v[mm], colacc[mm]);
        }
        __syncthreads();                     // s_buf no longer needed for staging
        if (h == 1) {
            #pragma unroll
            for (int mm = 0; mm < 8; mm++) s_buf[ht * 8 + mm] = colacc[mm];
        }
        __syncthreads();
        if (h == 0) {
            #pragma unroll
            for (int mm = 0; mm < 8; mm++)
                atomicAdd(&g_av[0][ht * 8 + mm], colacc[mm] + s_buf[ht * 8 + mm]);
        }
    }
    grid_barrier();

    // ================= 50 SINKHORN ITERATIONS =================
    for (int t = 0; t < ITERS; t++) {
        const bool last = (t == ITERS - 1);
        const float* a_rd = g_av[t % 3];
        float* a_wr       = g_av[(t + 1) % 3];
        float* a_zero     = g_av[(t + 2) % 3];
        const float* C_rd = g_Cb[t & 1];
        float* C_wr       = g_Cb[(t + 1) & 1];
        const float* R_rd = g_Rb[t & 1];
        float* R_wr       = g_Rb[(t + 1) & 1];
        const int rbase = bid * ROWS_PB + h * HROWS;

        // prologue: C' for my 8 columns -> registers
        float cs_r[8];
        {
            const float4* cp = reinterpret_cast<const float4*>(C_rd + ht * 8);
            const float4* ap = reinterpret_cast<const float4*>(a_rd + ht * 8);
            float4 c0 = __ldcg(cp), c1 = __ldcg(cp + 1);
            float4 a0 = __ldcg(ap), a1 = __ldcg(ap + 1);
            cs_r[0] = c0.x / fmaxf(c0.x * a0.x, EPSF);
            cs_r[1] = c0.y / fmaxf(c0.y * a0.y, EPSF);
            cs_r[2] = c0.z / fmaxf(c0.z * a0.z, EPSF);
            cs_r[3] = c0.w / fmaxf(c0.w * a0.w, EPSF);
            cs_r[4] = c1.x / fmaxf(c1.x * a1.x, EPSF);
            cs_r[5] = c1.y / fmaxf(c1.y * a1.y, EPSF);
            cs_r[6] = c1.z / fmaxf(c1.z * a1.z, EPSF);
            cs_r[7] = c1.w / fmaxf(c1.w * a1.w, EPSF);
        }
        if (tid < ROWS_PB) {
            int j = bid * ROWS_PB + tid;
            float Cj = __ldcg(&C_rd[j]), aj = __ldcg(&a_rd[j]);
            C_wr[j] = Cj / fmaxf(Cj * aj, EPSF);
            if (!last) a_zero[j] = 0.0f;
        }

        if (!last) {
            // --- pass 1: row dots, warp-pre-reduced, partials to smem ---
            #pragma unroll 4
            for (int r = 0; r < HROWS; r++) {
                uint4 q = reinterpret_cast<const uint4*>(g_mat + (size_t)(rbase + r) * NNV)[ht];
                float v[8]; unpack8(q, v);
                float d = 0.0f;
                #pragma unroll
                for (int mm = 0; mm < 8; mm++) d = fmaf(v[mm], cs_r[mm], d);
                d = wredsum(d);
                if (lane == 0) s_pb[h][r][hw] = d;
            }
            half_sync(h);
            // --- finalize rows: 16 threads per half ---
            if (ht < HROWS) {
                int i = rbase + ht;
                float b = 0.0f;
                #pragma unroll
                for (int k = 0; k < 16; k++) b += s_pb[h][ht][k];
                float Ro = __ldcg(&R_rd[i]);
                float Rn = Ro / fmaxf(Ro * b, EPSF);
                R_wr[i] = Rn;
                s_rn[h][ht] = Rn;
            }
            half_sync(h);
            // --- pass 2: colsums with fresh R (L1 re-read) ---
            float colacc[8];
            #pragma unroll
            for (int mm = 0; mm < 8; mm++) colacc[mm] = 0.0f;
            #pragma unroll 4
            for (int r = 0; r < HROWS; r++) {
                uint4 q = reinterpret_cast<const uint4*>(g_mat + (size_t)(rbase + r) * NNV)[ht];
                float v[8]; unpack8(q, v);
                float Rn = s_rn[h][r];
                #pragma unroll
                for (int mm = 0; mm < 8; mm++) colacc[mm] = fmaf(Rn, v[mm], colacc[mm]);
            }
            // --- combine halves in smem, single RED per column ---
            if (h == 1) {
                #pragma unroll
                for (int mm = 0; mm < 8; mm++) s_buf[ht * 8 + mm] = colacc[mm];
            }
            __syncthreads();
            if (h == 0) {
                #pragma unroll
                for (int mm = 0; mm < 8; mm++)
                    atomicAdd(&a_wr[ht * 8 + mm], colacc[mm] + s_buf[ht * 8 + mm]);
            }
        } else {
            // last iteration: fold DCG contraction (both dots in one sweep)
            float gs_r[8];
            #pragma unroll
            for (int mm = 0; mm < 8; mm++)
                gs_r[mm] = cs_r[mm] * (exp2f(target[ht * 8 + mm]) - 1.0f);
            #pragma unroll 4
            for (int r = 0; r < HROWS; r++) {
                uint4 q = reinterpret_cast<const uint4*>(g_mat + (size_t)(rbase + r) * NNV)[ht];
                float v[8]; unpack8(q, v);
                float d1 = 0.0f, d2 = 0.0f;
                #pragma unroll
                for (int mm = 0; mm < 8; mm++) {
                    d1 = fmaf(v[mm], cs_r[mm], d1);
                    d2 = fmaf(v[mm], gs_r[mm], d2);
                }
                d1 = wredsum(d1);
                d2 = wredsum(d2);
                if (lane == 0) { s_pb[h][r][hw] = d1; }
                if (lane == 1) { s_buf[(h * HROWS + r) * 16 + hw] = d2; }
            }
            half_sync(h);
            if (ht < HROWS) {
                int i = rbase + ht;
                float b = 0.0f, d = 0.0f;
                #pragma unroll
                for (int k = 0; k < 16; k++) {
                    b += s_pb[h][ht][k];
                    d += s_buf[(h * HROWS + ht) * 16 + k];
                }
                float Ro = __ldcg(&R_rd[i]);
                float Rn = Ro / fmaxf(Ro * b, EPSF);
                g_rowdcg[i] = Rn * d / log2f((float)i + 2.0f);
            }
        }
        grid_barrier();
    }

    // ================= FINAL =================
    if (bid == 0) {
        float part = 0.0f;
        #pragma unroll
        for (int k = 0; k < 4; k++) part += __ldcg(&g_rowdcg[tid * 4 + k]);
        part = wredsum(part);
        if (lane == 0) s_red[wid] = part;
        __syncthreads();
        if (tid == 0) {
            float dcg = 0.0f;
            for (int k = 0; k < 32; k++) dcg += s_red[k];
            float idcg = 0.0f;
            for (int k = 0; k < NBLK; k++) idcg += __ldcg(&g_idcgPart[k]);
            out[0] = -(dcg / (idcg + 1e-8f));
        }
    }
}

extern "C" void kernel_launch(void* const* d_in, const int* in_sizes, int n_in,
                              void* d_out, int out_size) {
    const float* pred   = (const float*)d_in[0];
    const float* target = (const float*)d_in[1];
    float* out = (float*)d_out;
    ndcg_kernel<<<NBLK, TPB>>>(pred, target, out);
}